// round 1
// baseline (speedup 1.0000x reference)
#include <cuda_runtime.h>

#define N 8192
#define JS 16            // j-dimension splits
#define TPB 256          // main kernel threads (= rows per CTA)
#define GX (N / TPB)     // 32
#define MAX_CHUNK 512    // ceil(8192/16)

__device__ float  g_l[N];
__device__ float  g_ang[N];
__device__ float4 g_keys[N];
__device__ int    g_M;
__device__ float  g_num[JS * N];
__device__ float  g_den[JS * N];

__device__ __forceinline__ float ex2f(float x) {
    float r;
    asm("ex2.approx.ftz.f32 %0, %1;" : "=f"(r) : "f"(x));
    return r;
}

// ---------------------------------------------------------------------------
// Kernel 1: lengths/angles, mean/std (unbiased), deterministic compaction.
// ---------------------------------------------------------------------------
__global__ __launch_bounds__(1024) void prep_kernel(const float* __restrict__ x) {
    __shared__ double sh_sum[1024];
    __shared__ double sh_sq[1024];
    __shared__ int    sh_cnt[1024];
    __shared__ float  sh_thr;

    const int t = threadIdx.x;
    float l[8], a[8];
    double sum = 0.0, sq = 0.0;

#pragma unroll
    for (int k = 0; k < 8; k++) {
        int i = t * 8 + k;
        float x0 = x[2 * i], x1 = x[2 * i + 1];
        float li = sqrtf(x0 * x0 + x1 * x1);
        float ai = atan2f(x1, x0);
        l[k] = li; a[k] = ai;
        g_l[i] = li;
        g_ang[i] = ai;
        sum += (double)li;
        sq  += (double)li * (double)li;
    }
    sh_sum[t] = sum; sh_sq[t] = sq;
    __syncthreads();
    for (int off = 512; off > 0; off >>= 1) {
        if (t < off) { sh_sum[t] += sh_sum[t + off]; sh_sq[t] += sh_sq[t + off]; }
        __syncthreads();
    }
    if (t == 0) {
        double s = sh_sum[0], s2 = sh_sq[0];
        double mean = s / (double)N;
        double var = (s2 - (double)N * mean * mean) / (double)(N - 1);
        double sd = sqrt(var > 0.0 ? var : 0.0);
        sh_thr = (float)(mean + 0.1 * sd);
    }
    __syncthreads();
    const float thr = sh_thr;

    int c = 0;
#pragma unroll
    for (int k = 0; k < 8; k++) c += (l[k] >= thr) ? 1 : 0;
    sh_cnt[t] = c;
    __syncthreads();

    // Hillis-Steele inclusive scan over 1024 thread counts (deterministic order)
    for (int off = 1; off < 1024; off <<= 1) {
        int u = (t >= off) ? sh_cnt[t - off] : 0;
        __syncthreads();
        sh_cnt[t] += u;
        __syncthreads();
    }

    int base = sh_cnt[t] - c;   // exclusive prefix
    const float HL2E = 0.5f * 1.4426950408889634f;
#pragma unroll
    for (int k = 0; k < 8; k++) {
        if (l[k] >= thr) {
            g_keys[base] = make_float4(l[k], HL2E * l[k] * l[k], a[k], 0.0f);
            base++;
        }
    }
    if (t == 1023) g_M = sh_cnt[1023];
}

// ---------------------------------------------------------------------------
// Kernel 2: per-row partial softmax-weighted sums over one j-chunk.
//   w_ij ∝ exp2(p_j - log2e*l_i*l_j)   (row-constant factor cancels in ratio)
// ---------------------------------------------------------------------------
__global__ __launch_bounds__(TPB) void main_kernel() {
    __shared__ float4 keys[MAX_CHUNK];

    const int M = g_M;
    const int y = blockIdx.y;
    const int j0 = (int)(((long long)M * y) / JS);
    const int j1 = (int)(((long long)M * (y + 1)) / JS);
    const int n = j1 - j0;

    for (int j = threadIdx.x; j < n; j += TPB) keys[j] = g_keys[j0 + j];
    __syncthreads();

    const int row = blockIdx.x * TPB + threadIdx.x;
    const float q = -1.4426950408889634f * g_l[row];

    float den0 = 0.f, den1 = 0.f, num0 = 0.f, num1 = 0.f;
    int j = 0;
    for (; j + 4 <= n; j += 4) {
        float4 k0 = keys[j], k1 = keys[j + 1], k2 = keys[j + 2], k3 = keys[j + 3];
        float e0 = ex2f(fmaf(q, k0.x, k0.y));
        float e1 = ex2f(fmaf(q, k1.x, k1.y));
        float e2 = ex2f(fmaf(q, k2.x, k2.y));
        float e3 = ex2f(fmaf(q, k3.x, k3.y));
        den0 += e0; num0 = fmaf(e0, k0.z, num0);
        den1 += e1; num1 = fmaf(e1, k1.z, num1);
        den0 += e2; num0 = fmaf(e2, k2.z, num0);
        den1 += e3; num1 = fmaf(e3, k3.z, num1);
    }
    for (; j < n; j++) {
        float4 k0 = keys[j];
        float e0 = ex2f(fmaf(q, k0.x, k0.y));
        den0 += e0; num0 = fmaf(e0, k0.z, num0);
    }

    g_den[y * N + row] = den0 + den1;
    g_num[y * N + row] = num0 + num1;
}

// ---------------------------------------------------------------------------
// Kernel 3: reduce partials (fixed order), emit (l*cos, l*sin).
// ---------------------------------------------------------------------------
__global__ void finish_kernel(float* __restrict__ out) {
    int row = blockIdx.x * blockDim.x + threadIdx.x;
    if (row >= N) return;
    float num = 0.f, den = 0.f;
#pragma unroll
    for (int y = 0; y < JS; y++) {
        num += g_num[y * N + row];
        den += g_den[y * N + row];
    }
    float th = num / den;
    float s, c;
    sincosf(th, &s, &c);
    float li = g_l[row];
    out[2 * row]     = li * c;
    out[2 * row + 1] = li * s;
}

extern "C" void kernel_launch(void* const* d_in, const int* in_sizes, int n_in,
                              void* d_out, int out_size) {
    const float* x = (const float*)d_in[0];
    float* out = (float*)d_out;

    prep_kernel<<<1, 1024>>>(x);
    main_kernel<<<dim3(GX, JS), TPB>>>();
    finish_kernel<<<(N + 255) / 256, 256>>>(out);
}

// round 2
// speedup vs baseline: 1.5191x; 1.5191x over previous
#include <cuda_runtime.h>

#define N 8192
#define JS 32            // j-dimension splits
#define TPB 256          // main kernel threads (= rows per CTA)
#define GX (N / TPB)     // 32
#define MAX_CHUNK 256    // ceil(8192/32)
#define SB 32            // stats blocks

__device__ float  g_l[N];
__device__ float  g_ang[N];
__device__ float4 g_keys[N];
__device__ int    g_M;
__device__ float  g_num[JS * N];
__device__ float  g_den[JS * N];
__device__ double g_psum[SB];
__device__ double g_psq[SB];

__device__ __forceinline__ float ex2f(float x) {
    float r;
    asm("ex2.approx.ftz.f32 %0, %1;" : "=f"(r) : "f"(x));
    return r;
}

// ---------------------------------------------------------------------------
// Kernel 1: lengths/angles + per-block double partial sums (32 CTAs).
// ---------------------------------------------------------------------------
__global__ __launch_bounds__(TPB) void stats_kernel(const float* __restrict__ x) {
    __shared__ double sh_sum[TPB];
    __shared__ double sh_sq[TPB];

    const int i = blockIdx.x * TPB + threadIdx.x;
    float2 xi = ((const float2*)x)[i];
    float li = sqrtf(xi.x * xi.x + xi.y * xi.y);
    float ai = atan2f(xi.y, xi.x);
    g_l[i] = li;
    g_ang[i] = ai;

    sh_sum[threadIdx.x] = (double)li;
    sh_sq[threadIdx.x]  = (double)li * (double)li;
    __syncthreads();
    for (int off = TPB / 2; off > 0; off >>= 1) {
        if (threadIdx.x < off) {
            sh_sum[threadIdx.x] += sh_sum[threadIdx.x + off];
            sh_sq[threadIdx.x]  += sh_sq[threadIdx.x + off];
        }
        __syncthreads();
    }
    if (threadIdx.x == 0) {
        g_psum[blockIdx.x] = sh_sum[0];
        g_psq[blockIdx.x]  = sh_sq[0];
    }
}

// ---------------------------------------------------------------------------
// Kernel 2: threshold + deterministic compaction (1 CTA, no transcendentals).
// ---------------------------------------------------------------------------
__global__ __launch_bounds__(1024) void compact_kernel() {
    __shared__ int   sh_cnt[1024];
    __shared__ float sh_thr;

    const int t = threadIdx.x;

    if (t < 32) {
        double s  = g_psum[t];
        double s2 = g_psq[t];
        for (int off = 16; off > 0; off >>= 1) {
            s  += __shfl_down_sync(0xffffffffu, s,  off);
            s2 += __shfl_down_sync(0xffffffffu, s2, off);
        }
        if (t == 0) {
            double mean = s / (double)N;
            double var = (s2 - (double)N * mean * mean) / (double)(N - 1);
            double sd = sqrt(var > 0.0 ? var : 0.0);
            sh_thr = (float)(mean + 0.1 * sd);
        }
    }
    __syncthreads();
    const float thr = sh_thr;

    float l[8];
    float4 lo = ((const float4*)g_l)[t * 2];
    float4 hi = ((const float4*)g_l)[t * 2 + 1];
    l[0] = lo.x; l[1] = lo.y; l[2] = lo.z; l[3] = lo.w;
    l[4] = hi.x; l[5] = hi.y; l[6] = hi.z; l[7] = hi.w;

    int c = 0;
#pragma unroll
    for (int k = 0; k < 8; k++) c += (l[k] >= thr) ? 1 : 0;
    sh_cnt[t] = c;
    __syncthreads();

    // Hillis-Steele inclusive scan over 1024 thread counts (deterministic order)
    for (int off = 1; off < 1024; off <<= 1) {
        int u = (t >= off) ? sh_cnt[t - off] : 0;
        __syncthreads();
        sh_cnt[t] += u;
        __syncthreads();
    }

    int base = sh_cnt[t] - c;   // exclusive prefix
    const float HL2E = 0.5f * 1.4426950408889634f;
#pragma unroll
    for (int k = 0; k < 8; k++) {
        if (l[k] >= thr) {
            int i = t * 8 + k;
            g_keys[base] = make_float4(l[k], HL2E * l[k] * l[k], g_ang[i], 0.0f);
            base++;
        }
    }
    if (t == 1023) g_M = sh_cnt[1023];
}

// ---------------------------------------------------------------------------
// Kernel 3: per-row partial softmax-weighted sums over one j-chunk.
//   w_ij ∝ exp2(p_j - log2e*l_i*l_j)   (row-constant factor cancels in ratio)
// ---------------------------------------------------------------------------
__global__ __launch_bounds__(TPB) void main_kernel() {
    __shared__ float4 keys[MAX_CHUNK];

    const int M = g_M;
    const int y = blockIdx.y;
    const int j0 = (int)(((long long)M * y) / JS);
    const int j1 = (int)(((long long)M * (y + 1)) / JS);
    const int n = j1 - j0;

    for (int j = threadIdx.x; j < n; j += TPB) keys[j] = g_keys[j0 + j];
    __syncthreads();

    const int row = blockIdx.x * TPB + threadIdx.x;
    const float q = -1.4426950408889634f * g_l[row];

    float den0 = 0.f, den1 = 0.f, num0 = 0.f, num1 = 0.f;
    int j = 0;
    for (; j + 4 <= n; j += 4) {
        float4 k0 = keys[j], k1 = keys[j + 1], k2 = keys[j + 2], k3 = keys[j + 3];
        float e0 = ex2f(fmaf(q, k0.x, k0.y));
        float e1 = ex2f(fmaf(q, k1.x, k1.y));
        float e2 = ex2f(fmaf(q, k2.x, k2.y));
        float e3 = ex2f(fmaf(q, k3.x, k3.y));
        den0 += e0; num0 = fmaf(e0, k0.z, num0);
        den1 += e1; num1 = fmaf(e1, k1.z, num1);
        den0 += e2; num0 = fmaf(e2, k2.z, num0);
        den1 += e3; num1 = fmaf(e3, k3.z, num1);
    }
    for (; j < n; j++) {
        float4 k0 = keys[j];
        float e0 = ex2f(fmaf(q, k0.x, k0.y));
        den0 += e0; num0 = fmaf(e0, k0.z, num0);
    }

    g_den[y * N + row] = den0 + den1;
    g_num[y * N + row] = num0 + num1;
}

// ---------------------------------------------------------------------------
// Kernel 4: reduce partials (fixed order), emit (l*cos, l*sin).
// ---------------------------------------------------------------------------
__global__ void finish_kernel(float* __restrict__ out) {
    int row = blockIdx.x * blockDim.x + threadIdx.x;
    if (row >= N) return;
    float num = 0.f, den = 0.f;
#pragma unroll
    for (int y = 0; y < JS; y++) {
        num += g_num[y * N + row];
        den += g_den[y * N + row];
    }
    float th = num / den;
    float s, c;
    sincosf(th, &s, &c);
    float li = g_l[row];
    out[2 * row]     = li * c;
    out[2 * row + 1] = li * s;
}

extern "C" void kernel_launch(void* const* d_in, const int* in_sizes, int n_in,
                              void* d_out, int out_size) {
    const float* x = (const float*)d_in[0];
    float* out = (float*)d_out;

    stats_kernel<<<SB, TPB>>>(x);
    compact_kernel<<<1, 1024>>>();
    main_kernel<<<dim3(GX, JS), TPB>>>();
    finish_kernel<<<(N + 255) / 256, 256>>>(out);
}